// round 2
// baseline (speedup 1.0000x reference)
#include <cuda_runtime.h>
#include <cstdint>

// Problem constants
#define Bsz   4
#define Ssz   4096
#define Dsz   1024
#define GROUP 256
#define HEAD  128
#define INNER 2048
#define NGRP  (Bsz * (Ssz / GROUP))   // 64 groups total (chunks contiguous in token order)
#define MTOT  (Bsz * Ssz)             // 16384 tokens

// Scratch (device globals — no allocation allowed in kernel_launch)
__device__ float g_v   [(size_t)MTOT * INNER];     // silu(x@Wv+bv)
__device__ float g_gate[(size_t)MTOT * INNER];     // silu(x@Wg+bg)
__device__ float g_xh  [(size_t)MTOT * HEAD];      // silu(x@Win+bin)
__device__ float g_o   [(size_t)MTOT * INNER];     // v_quad, then (v_quad+v_lin)*gate
__device__ float g_attn[(size_t)NGRP * GROUP * GROUP];
__device__ float g_kv  [(size_t)NGRP * HEAD * INNER];

__device__ __forceinline__ float silu_f(float x) { return x / (1.0f + __expf(-x)); }

// Fragment row/col mapping: split 8 into 4+4 at 64 offset (reduces smem bank conflicts)
__device__ __forceinline__ int frag_idx(int base4, int i) {
    return (i < 4) ? (base4 + i) : (64 + base4 + i - 4);
}

#define MICRO_LOOP()                                                          \
    _Pragma("unroll")                                                         \
    for (int k = 0; k < 16; k++) {                                            \
        float a[8], b[8];                                                     \
        *(float4*)&a[0] = *(const float4*)&As[k][ty4];                        \
        *(float4*)&a[4] = *(const float4*)&As[k][64 + ty4];                   \
        *(float4*)&b[0] = *(const float4*)&Bs[k][tx4];                        \
        *(float4*)&b[4] = *(const float4*)&Bs[k][64 + tx4];                   \
        _Pragma("unroll")                                                     \
        for (int i = 0; i < 8; i++)                                           \
            _Pragma("unroll")                                                 \
            for (int j = 0; j < 8; j++)                                       \
                acc[i][j] = fmaf(a[i], b[j], acc[i][j]);                      \
    }

// ---------------------------------------------------------------------------
// Generic GEMM: C[M,N] = act(A[M,K] @ W[K,N] + bias[N]); all dims % 128 == 0
// (N may be 128). ACT: 0 = identity, 1 = silu.
// ---------------------------------------------------------------------------
template <int ACT>
__global__ void gemm_bias_act(const float* __restrict__ A,
                              const float* __restrict__ W,
                              const float* __restrict__ bias,
                              float* __restrict__ C,
                              int M, int N, int K) {
    __shared__ float As[16][128];
    __shared__ float Bs[16][128];
    const int tid = threadIdx.x;
    const int tx = tid & 15, ty = tid >> 4;
    const int tx4 = tx * 4, ty4 = ty * 4;
    const int bm = blockIdx.y * 128, bn = blockIdx.x * 128;

    float acc[8][8] = {};
    for (int k0 = 0; k0 < K; k0 += 16) {
        // A tile: 128 rows x 16 k, float4 along k, store transposed As[k][m]
        #pragma unroll
        for (int t = 0; t < 2; t++) {
            int f  = tid + t * 256;       // 0..511
            int r  = f >> 2;              // 0..127
            int c4 = (f & 3) * 4;         // 0,4,8,12
            float4 av = *(const float4*)&A[(size_t)(bm + r) * K + k0 + c4];
            As[c4 + 0][r] = av.x; As[c4 + 1][r] = av.y;
            As[c4 + 2][r] = av.z; As[c4 + 3][r] = av.w;
        }
        // W tile: 16 k x 128 n, direct
        #pragma unroll
        for (int t = 0; t < 2; t++) {
            int f  = tid + t * 256;
            int r  = f >> 5;              // 0..15
            int c4 = (f & 31) * 4;        // 0..124
            *(float4*)&Bs[r][c4] = *(const float4*)&W[(size_t)(k0 + r) * N + bn + c4];
        }
        __syncthreads();
        MICRO_LOOP();
        __syncthreads();
    }
    #pragma unroll
    for (int i = 0; i < 8; i++) {
        int r = bm + frag_idx(ty4, i);
        #pragma unroll
        for (int j = 0; j < 8; j++) {
            int c = bn + frag_idx(tx4, j);
            float v = acc[i][j] + bias[c];
            if (ACT == 1) v = silu_f(v);
            C[(size_t)r * N + c] = v;
        }
    }
}

// ---------------------------------------------------------------------------
// Per-group attention scores: attn = relu(mask(qq @ qkT / sqrt(INNER)))^2
// qq/qk are affine transforms of x_ chunk. grid (2, 2, NGRP)
// ---------------------------------------------------------------------------
__global__ void attn_kernel(const float* __restrict__ xh,
                            const float* __restrict__ gqq, const float* __restrict__ bqq,
                            const float* __restrict__ gqk, const float* __restrict__ bqk,
                            float* __restrict__ attn) {
    __shared__ float As[16][128];   // [k][m]  (qq)
    __shared__ float Bs[16][128];   // [k][n]  (qk)
    const int tid = threadIdx.x;
    const int tx = tid & 15, ty = tid >> 4;
    const int tx4 = tx * 4, ty4 = ty * 4;
    const int grp = blockIdx.z;
    const int bm = blockIdx.y * 128, bn = blockIdx.x * 128;
    const float* xb = xh + (size_t)grp * GROUP * HEAD;

    float acc[8][8] = {};
    for (int k0 = 0; k0 < HEAD; k0 += 16) {
        #pragma unroll
        for (int t = 0; t < 2; t++) {
            int f  = tid + t * 256;
            int r  = f >> 2;
            int c4 = (f & 3) * 4;
            float4 gq = *(const float4*)&gqq[k0 + c4];
            float4 oq = *(const float4*)&bqq[k0 + c4];
            float4 gk = *(const float4*)&gqk[k0 + c4];
            float4 ok = *(const float4*)&bqk[k0 + c4];
            float4 xq = *(const float4*)&xb[(size_t)(bm + r) * HEAD + k0 + c4];
            As[c4 + 0][r] = xq.x * gq.x + oq.x;
            As[c4 + 1][r] = xq.y * gq.y + oq.y;
            As[c4 + 2][r] = xq.z * gq.z + oq.z;
            As[c4 + 3][r] = xq.w * gq.w + oq.w;
            float4 xk = *(const float4*)&xb[(size_t)(bn + r) * HEAD + k0 + c4];
            Bs[c4 + 0][r] = xk.x * gk.x + ok.x;
            Bs[c4 + 1][r] = xk.y * gk.y + ok.y;
            Bs[c4 + 2][r] = xk.z * gk.z + ok.z;
            Bs[c4 + 3][r] = xk.w * gk.w + ok.w;
        }
        __syncthreads();
        MICRO_LOOP();
        __syncthreads();
    }
    const float inv_scale = 0.022097086912079608f;  // 1/sqrt(2048)
    float* ab = attn + (size_t)grp * GROUP * GROUP;
    #pragma unroll
    for (int i = 0; i < 8; i++) {
        int r = bm + frag_idx(ty4, i);
        #pragma unroll
        for (int j = 0; j < 8; j++) {
            int c = bn + frag_idx(tx4, j);
            float s = acc[i][j] * inv_scale;
            s = (c <= r && s > 0.0f) ? s * s : 0.0f;
            ab[(size_t)r * GROUP + c] = s;
        }
    }
}

// ---------------------------------------------------------------------------
// v_quad = attn @ v  (per group: 256x2048 = [256,256]@[256,2048]); writes g_o.
// grid (16, 2, NGRP)
// ---------------------------------------------------------------------------
__global__ void vquad_kernel(const float* __restrict__ attn,
                             const float* __restrict__ v,
                             float* __restrict__ o) {
    __shared__ float As[16][128];
    __shared__ float Bs[16][128];
    const int tid = threadIdx.x;
    const int tx = tid & 15, ty = tid >> 4;
    const int tx4 = tx * 4, ty4 = ty * 4;
    const int grp = blockIdx.z;
    const int bm = blockIdx.y * 128, bn = blockIdx.x * 128;
    const float* Ab = attn + (size_t)grp * GROUP * GROUP;
    const float* Vb = v + (size_t)grp * GROUP * INNER;
    float* Ob = o + (size_t)grp * GROUP * INNER;

    float acc[8][8] = {};
    for (int k0 = 0; k0 < GROUP; k0 += 16) {
        #pragma unroll
        for (int t = 0; t < 2; t++) {
            int f = tid + t * 256;
            int r = f >> 2;
            int c4 = (f & 3) * 4;
            float4 av = *(const float4*)&Ab[(size_t)(bm + r) * GROUP + k0 + c4];
            As[c4 + 0][r] = av.x; As[c4 + 1][r] = av.y;
            As[c4 + 2][r] = av.z; As[c4 + 3][r] = av.w;
        }
        #pragma unroll
        for (int t = 0; t < 2; t++) {
            int f = tid + t * 256;
            int r = f >> 5;
            int c4 = (f & 31) * 4;
            *(float4*)&Bs[r][c4] = *(const float4*)&Vb[(size_t)(k0 + r) * INNER + bn + c4];
        }
        __syncthreads();
        MICRO_LOOP();
        __syncthreads();
    }
    #pragma unroll
    for (int i = 0; i < 8; i++) {
        int r = bm + frag_idx(ty4, i);
        #pragma unroll
        for (int j = 0; j < 8; j++) {
            int c = bn + frag_idx(tx4, j);
            Ob[(size_t)r * INNER + c] = acc[i][j];
        }
    }
}

// ---------------------------------------------------------------------------
// kv[h,e] = sum_c lin_k[c,h] * v[c,e] per group (A^T @ B, M=128, N=2048, K=256)
// grid (16, 1, NGRP)
// ---------------------------------------------------------------------------
__global__ void kv_kernel(const float* __restrict__ xh,
                          const float* __restrict__ glk, const float* __restrict__ blk,
                          const float* __restrict__ v,
                          float* __restrict__ kv) {
    __shared__ float As[16][128];   // [c][h] — natural layout, no transpose needed
    __shared__ float Bs[16][128];   // [c][e]
    const int tid = threadIdx.x;
    const int tx = tid & 15, ty = tid >> 4;
    const int tx4 = tx * 4, ty4 = ty * 4;
    const int grp = blockIdx.z;
    const int bn = blockIdx.x * 128;
    const float* xb = xh + (size_t)grp * GROUP * HEAD;
    const float* Vb = v + (size_t)grp * GROUP * INNER;

    float acc[8][8] = {};
    for (int c0 = 0; c0 < GROUP; c0 += 16) {
        #pragma unroll
        for (int t = 0; t < 2; t++) {
            int f = tid + t * 256;
            int r = f >> 5;                // 0..15 (c)
            int c4 = (f & 31) * 4;         // 0..124 (h)
            float4 xv = *(const float4*)&xb[(size_t)(c0 + r) * HEAD + c4];
            float4 gv = *(const float4*)&glk[c4];
            float4 bv = *(const float4*)&blk[c4];
            float4 lk;
            lk.x = xv.x * gv.x + bv.x; lk.y = xv.y * gv.y + bv.y;
            lk.z = xv.z * gv.z + bv.z; lk.w = xv.w * gv.w + bv.w;
            *(float4*)&As[r][c4] = lk;
        }
        #pragma unroll
        for (int t = 0; t < 2; t++) {
            int f = tid + t * 256;
            int r = f >> 5;
            int c4 = (f & 31) * 4;
            *(float4*)&Bs[r][c4] = *(const float4*)&Vb[(size_t)(c0 + r) * INNER + bn + c4];
        }
        __syncthreads();
        MICRO_LOOP();
        __syncthreads();
    }
    float* Kb = kv + (size_t)grp * HEAD * INNER;
    #pragma unroll
    for (int i = 0; i < 8; i++) {
        int h = frag_idx(ty4, i);          // 0..127
        #pragma unroll
        for (int j = 0; j < 8; j++) {
            int e = bn + frag_idx(tx4, j);
            Kb[(size_t)h * INNER + e] = acc[i][j];
        }
    }
}

// ---------------------------------------------------------------------------
// Exclusive cumsum of kv over chunk dim within each batch (16 chunks, sequential)
// ---------------------------------------------------------------------------
__global__ void kv_cumsum_kernel(float* __restrict__ kv) {
    const int idx = blockIdx.x * blockDim.x + threadIdx.x;   // B*HEAD*INNER
    const int b = idx / (HEAD * INNER);
    const int he = idx % (HEAD * INNER);
    const int GPB = Ssz / GROUP;   // 16
    float run = 0.0f;
    for (int g = 0; g < GPB; g++) {
        size_t off = ((size_t)(b * GPB + g) * HEAD * INNER) + he;
        float t = kv[off];
        kv[off] = run;
        run += t;
    }
}

// ---------------------------------------------------------------------------
// v_lin = lin_q @ kv_excl; o = (v_quad + v_lin) * gate    (per group)
// M=256, N=2048, K=128. grid (16, 2, NGRP)
// ---------------------------------------------------------------------------
__global__ void vlin_gate_kernel(const float* __restrict__ xh,
                                 const float* __restrict__ glq, const float* __restrict__ blq,
                                 const float* __restrict__ kv,
                                 const float* __restrict__ gate,
                                 float* __restrict__ o) {
    __shared__ float As[16][128];
    __shared__ float Bs[16][128];
    const int tid = threadIdx.x;
    const int tx = tid & 15, ty = tid >> 4;
    const int tx4 = tx * 4, ty4 = ty * 4;
    const int grp = blockIdx.z;
    const int bm = blockIdx.y * 128, bn = blockIdx.x * 128;
    const float* xb = xh + (size_t)grp * GROUP * HEAD;
    const float* Kb = kv + (size_t)grp * HEAD * INNER;
    const float* Gb = gate + (size_t)grp * GROUP * INNER;
    float* Ob = o + (size_t)grp * GROUP * INNER;

    float acc[8][8] = {};
    for (int k0 = 0; k0 < HEAD; k0 += 16) {
        #pragma unroll
        for (int t = 0; t < 2; t++) {
            int f = tid + t * 256;
            int r = f >> 2;
            int c4 = (f & 3) * 4;
            float4 xv = *(const float4*)&xb[(size_t)(bm + r) * HEAD + k0 + c4];
            float4 gv = *(const float4*)&glq[k0 + c4];
            float4 bv = *(const float4*)&blq[k0 + c4];
            As[c4 + 0][r] = xv.x * gv.x + bv.x;
            As[c4 + 1][r] = xv.y * gv.y + bv.y;
            As[c4 + 2][r] = xv.z * gv.z + bv.z;
            As[c4 + 3][r] = xv.w * gv.w + bv.w;
        }
        #pragma unroll
        for (int t = 0; t < 2; t++) {
            int f = tid + t * 256;
            int r = f >> 5;
            int c4 = (f & 31) * 4;
            *(float4*)&Bs[r][c4] = *(const float4*)&Kb[(size_t)(k0 + r) * INNER + bn + c4];
        }
        __syncthreads();
        MICRO_LOOP();
        __syncthreads();
    }
    #pragma unroll
    for (int i = 0; i < 8; i++) {
        int r = bm + frag_idx(ty4, i);
        #pragma unroll
        for (int j = 0; j < 8; j++) {
            int c = bn + frag_idx(tx4, j);
            size_t off = (size_t)r * INNER + c;
            Ob[off] = (Ob[off] + acc[i][j]) * Gb[off];
        }
    }
}

// ---------------------------------------------------------------------------
extern "C" void kernel_launch(void* const* d_in, const int* in_sizes, int n_in,
                              void* d_out, int out_size) {
    const float* x    = (const float*)d_in[0];
    const float* Wv   = (const float*)d_in[1];
    const float* bv   = (const float*)d_in[2];
    const float* Wg   = (const float*)d_in[3];
    const float* bg   = (const float*)d_in[4];
    const float* Win  = (const float*)d_in[5];
    const float* bin_ = (const float*)d_in[6];
    const float* Wout = (const float*)d_in[7];
    const float* bout = (const float*)d_in[8];
    const float* gqq  = (const float*)d_in[9];
    const float* bqq  = (const float*)d_in[10];
    const float* gqk  = (const float*)d_in[11];
    const float* bqk  = (const float*)d_in[12];
    const float* glq  = (const float*)d_in[13];
    const float* blq  = (const float*)d_in[14];
    const float* glk  = (const float*)d_in[15];
    const float* blk  = (const float*)d_in[16];
    float* out = (float*)d_out;

    float *pv, *pgate, *pxh, *po, *pattn, *pkv;
    cudaGetSymbolAddress((void**)&pv,    g_v);
    cudaGetSymbolAddress((void**)&pgate, g_gate);
    cudaGetSymbolAddress((void**)&pxh,   g_xh);
    cudaGetSymbolAddress((void**)&po,    g_o);
    cudaGetSymbolAddress((void**)&pattn, g_attn);
    cudaGetSymbolAddress((void**)&pkv,   g_kv);

    dim3 blk256(256);

    // 1-3. input projections
    gemm_bias_act<1><<<dim3(INNER / 128, MTOT / 128), blk256>>>(x, Wv, bv, pv, MTOT, INNER, Dsz);
    gemm_bias_act<1><<<dim3(INNER / 128, MTOT / 128), blk256>>>(x, Wg, bg, pgate, MTOT, INNER, Dsz);
    gemm_bias_act<1><<<dim3(HEAD / 128, MTOT / 128), blk256>>>(x, Win, bin_, pxh, MTOT, HEAD, Dsz);

    // 4. attention scores per chunk
    attn_kernel<<<dim3(2, 2, NGRP), blk256>>>(pxh, gqq, bqq, gqk, bqk, pattn);

    // 5. v_quad = attn @ v
    vquad_kernel<<<dim3(INNER / 128, GROUP / 128, NGRP), blk256>>>(pattn, pv, po);

    // 6. per-chunk kv = lin_k^T @ v
    kv_kernel<<<dim3(INNER / 128, 1, NGRP), blk256>>>(pxh, glk, blk, pv, pkv);

    // 7. exclusive chunk cumsum
    kv_cumsum_kernel<<<dim3((Bsz * HEAD * INNER) / 256), blk256>>>(pkv);

    // 8. v_lin = lin_q @ kv; o = (v_quad + v_lin) * gate
    vlin_gate_kernel<<<dim3(INNER / 128, GROUP / 128, NGRP), blk256>>>(pxh, glq, blq, pkv, pgate, po);

    // 9. out = o @ Wout + bout
    gemm_bias_act<0><<<dim3(Dsz / 128, MTOT / 128), blk256>>>(po, Wout, bout, out, MTOT, Dsz, INNER);
}

// round 3
// speedup vs baseline: 2.0832x; 2.0832x over previous
#include <cuda_runtime.h>
#include <cstdint>

// Problem constants
#define Bsz   4
#define Ssz   4096
#define Dsz   1024
#define GROUP 256
#define HEAD  128
#define INNER 2048
#define NGRP  (Bsz * (Ssz / GROUP))   // 64 groups
#define MTOT  (Bsz * Ssz)             // 16384 tokens

// Scratch (device globals — no allocation allowed)
__device__ float g_v   [(size_t)MTOT * INNER];
__device__ float g_gate[(size_t)MTOT * INNER];
__device__ float g_xh  [(size_t)MTOT * HEAD];
__device__ float g_o   [(size_t)MTOT * INNER];
__device__ float g_attn[(size_t)NGRP * GROUP * GROUP];
__device__ float g_kv  [(size_t)NGRP * HEAD * INNER];

__device__ __forceinline__ float silu_f(float x) { return x / (1.0f + __expf(-x)); }

__device__ __forceinline__ unsigned f2tf(float f) {
    unsigned u; asm("cvt.rna.tf32.f32 %0, %1;" : "=r"(u) : "f"(f)); return u;
}

__device__ __forceinline__ void mma_tf32(float c[4], const unsigned a[4], const unsigned b[2]) {
    asm("mma.sync.aligned.m16n8k8.row.col.f32.tf32.tf32.f32 "
        "{%0,%1,%2,%3}, {%4,%5,%6,%7}, {%8,%9}, {%0,%1,%2,%3};"
        : "+f"(c[0]), "+f"(c[1]), "+f"(c[2]), "+f"(c[3])
        : "r"(a[0]), "r"(a[1]), "r"(a[2]), "r"(a[3]), "r"(b[0]), "r"(b[1]));
}

// Smem tiles: [k=16][136] tf32 bits; stride 136 -> bank = (8k+m)%32 is conflict-free
#define SMS 136

// Warp-level K=16 compute step. acc[mt][nt][4]. wm in {0,64}, wn in {0,32,64,96}.
__device__ __forceinline__ void warp_mma_k16(float acc[4][4][4],
        const unsigned (*As)[SMS], const unsigned (*Bs)[SMS],
        int wm, int wn, int lane) {
    const int gm = lane >> 2;
    #pragma unroll
    for (int kk = 0; kk < 16; kk += 8) {
        const int kr = kk + (lane & 3);
        unsigned a[4][4], b[4][2];
        #pragma unroll
        for (int mt = 0; mt < 4; mt++) {
            int m = wm + mt * 16 + gm;
            a[mt][0] = As[kr][m];
            a[mt][1] = As[kr][m + 8];
            a[mt][2] = As[kr + 4][m];
            a[mt][3] = As[kr + 4][m + 8];
        }
        #pragma unroll
        for (int nt = 0; nt < 4; nt++) {
            int n = wn + nt * 8 + gm;
            b[nt][0] = Bs[kr][n];
            b[nt][1] = Bs[kr + 4][n];
        }
        #pragma unroll
        for (int mt = 0; mt < 4; mt++)
            #pragma unroll
            for (int nt = 0; nt < 4; nt++)
                mma_tf32(acc[mt][nt], a[mt], b[nt]);
    }
}

// Common per-thread tile coords
#define TILE_SETUP()                                   \
    const int tid  = threadIdx.x;                      \
    const int lane = tid & 31;                         \
    const int wid  = tid >> 5;                         \
    const int wm   = (wid >> 2) * 64;                  \
    const int wn   = (wid & 3) * 32;                   \
    float acc[4][4][4] = {};

// Load A tile (128 rows x 16 k, row-major source) transposed into As[k][m], tf32
#define LOAD_A_TRANS(SRC_EXPR)                                                \
    _Pragma("unroll")                                                         \
    for (int t = 0; t < 2; t++) {                                             \
        int f  = tid + t * 256;                                               \
        int r  = f >> 2;                                                      \
        int c4 = (f & 3) * 4;                                                 \
        float4 av = (SRC_EXPR);                                               \
        As[c4 + 0][r] = f2tf(av.x); As[c4 + 1][r] = f2tf(av.y);               \
        As[c4 + 2][r] = f2tf(av.z); As[c4 + 3][r] = f2tf(av.w);               \
    }

// Load B tile (16 k x 128 n, row-major source) direct into Bs[k][n], tf32
#define LOAD_B_DIRECT(SRC_EXPR)                                               \
    _Pragma("unroll")                                                         \
    for (int t = 0; t < 2; t++) {                                             \
        int f  = tid + t * 256;                                               \
        int r  = f >> 5;                                                      \
        int c4 = (f & 31) * 4;                                                \
        float4 wv = (SRC_EXPR);                                               \
        uint4 u = make_uint4(f2tf(wv.x), f2tf(wv.y), f2tf(wv.z), f2tf(wv.w)); \
        *(uint4*)&Bs[r][c4] = u;                                              \
    }

// ---------------------------------------------------------------------------
// Generic GEMM: C = act(A[M,K] @ W[K,N] + bias); dims % 128 == 0
// ---------------------------------------------------------------------------
template <int ACT>
__global__ __launch_bounds__(256, 2)
void gemm_bias_act(const float* __restrict__ A, const float* __restrict__ W,
                   const float* __restrict__ bias, float* __restrict__ C,
                   int M, int N, int K) {
    __shared__ unsigned As[16][SMS];
    __shared__ unsigned Bs[16][SMS];
    TILE_SETUP();
    const int bm = blockIdx.y * 128, bn = blockIdx.x * 128;

    for (int k0 = 0; k0 < K; k0 += 16) {
        LOAD_A_TRANS(*(const float4*)&A[(size_t)(bm + r) * K + k0 + c4]);
        LOAD_B_DIRECT(*(const float4*)&W[(size_t)(k0 + r) * N + bn + c4]);
        __syncthreads();
        warp_mma_k16(acc, As, Bs, wm, wn, lane);
        __syncthreads();
    }
    #pragma unroll
    for (int mt = 0; mt < 4; mt++) {
        int r0 = bm + wm + mt * 16 + (lane >> 2);
        #pragma unroll
        for (int nt = 0; nt < 4; nt++) {
            int c = bn + wn + nt * 8 + (lane & 3) * 2;
            float b0 = bias[c], b1 = bias[c + 1];
            float2 v0 = make_float2(acc[mt][nt][0] + b0, acc[mt][nt][1] + b1);
            float2 v1 = make_float2(acc[mt][nt][2] + b0, acc[mt][nt][3] + b1);
            if (ACT == 1) {
                v0.x = silu_f(v0.x); v0.y = silu_f(v0.y);
                v1.x = silu_f(v1.x); v1.y = silu_f(v1.y);
            }
            *(float2*)&C[(size_t)r0 * N + c] = v0;
            *(float2*)&C[(size_t)(r0 + 8) * N + c] = v1;
        }
    }
}

// ---------------------------------------------------------------------------
// attn = relu(mask(qq @ qk^T / sqrt(INNER)))^2 per group. grid (2, 2, NGRP)
// ---------------------------------------------------------------------------
__global__ __launch_bounds__(256, 2)
void attn_kernel(const float* __restrict__ xh,
                 const float* __restrict__ gqq, const float* __restrict__ bqq,
                 const float* __restrict__ gqk, const float* __restrict__ bqk,
                 float* __restrict__ attn) {
    __shared__ unsigned As[16][SMS];
    __shared__ unsigned Bs[16][SMS];
    TILE_SETUP();
    const int grp = blockIdx.z;
    const int bm = blockIdx.y * 128, bn = blockIdx.x * 128;
    const float* xb = xh + (size_t)grp * GROUP * HEAD;

    for (int k0 = 0; k0 < HEAD; k0 += 16) {
        #pragma unroll
        for (int t = 0; t < 2; t++) {
            int f  = tid + t * 256;
            int r  = f >> 2;
            int c4 = (f & 3) * 4;
            float4 gq = *(const float4*)&gqq[k0 + c4];
            float4 oq = *(const float4*)&bqq[k0 + c4];
            float4 xq = *(const float4*)&xb[(size_t)(bm + r) * HEAD + k0 + c4];
            As[c4 + 0][r] = f2tf(xq.x * gq.x + oq.x);
            As[c4 + 1][r] = f2tf(xq.y * gq.y + oq.y);
            As[c4 + 2][r] = f2tf(xq.z * gq.z + oq.z);
            As[c4 + 3][r] = f2tf(xq.w * gq.w + oq.w);
            float4 gk = *(const float4*)&gqk[k0 + c4];
            float4 ok = *(const float4*)&bqk[k0 + c4];
            float4 xk = *(const float4*)&xb[(size_t)(bn + r) * HEAD + k0 + c4];
            Bs[c4 + 0][r] = f2tf(xk.x * gk.x + ok.x);
            Bs[c4 + 1][r] = f2tf(xk.y * gk.y + ok.y);
            Bs[c4 + 2][r] = f2tf(xk.z * gk.z + ok.z);
            Bs[c4 + 3][r] = f2tf(xk.w * gk.w + ok.w);
        }
        __syncthreads();
        warp_mma_k16(acc, As, Bs, wm, wn, lane);
        __syncthreads();
    }
    const float inv_scale = 0.022097086912079608f;  // 1/sqrt(2048)
    float* ab = attn + (size_t)grp * GROUP * GROUP;
    #pragma unroll
    for (int mt = 0; mt < 4; mt++) {
        int r0 = bm + wm + mt * 16 + (lane >> 2);
        #pragma unroll
        for (int nt = 0; nt < 4; nt++) {
            int c = bn + wn + nt * 8 + (lane & 3) * 2;
            float s[4];
            #pragma unroll
            for (int q = 0; q < 4; q++) {
                int rr = r0 + (q >> 1) * 8;
                int cc = c + (q & 1);
                float v = acc[mt][nt][q] * inv_scale;
                s[q] = (cc <= rr && v > 0.0f) ? v * v : 0.0f;
            }
            *(float2*)&ab[(size_t)r0 * GROUP + c] = make_float2(s[0], s[1]);
            *(float2*)&ab[(size_t)(r0 + 8) * GROUP + c] = make_float2(s[2], s[3]);
        }
    }
}

// ---------------------------------------------------------------------------
// v_quad = attn @ v per group. grid (16, 2, NGRP)
// ---------------------------------------------------------------------------
__global__ __launch_bounds__(256, 2)
void vquad_kernel(const float* __restrict__ attn, const float* __restrict__ v,
                  float* __restrict__ o) {
    __shared__ unsigned As[16][SMS];
    __shared__ unsigned Bs[16][SMS];
    TILE_SETUP();
    const int grp = blockIdx.z;
    const int bm = blockIdx.y * 128, bn = blockIdx.x * 128;
    const float* Ab = attn + (size_t)grp * GROUP * GROUP;
    const float* Vb = v + (size_t)grp * GROUP * INNER;
    float* Ob = o + (size_t)grp * GROUP * INNER;

    for (int k0 = 0; k0 < GROUP; k0 += 16) {
        LOAD_A_TRANS(*(const float4*)&Ab[(size_t)(bm + r) * GROUP + k0 + c4]);
        LOAD_B_DIRECT(*(const float4*)&Vb[(size_t)(k0 + r) * INNER + bn + c4]);
        __syncthreads();
        warp_mma_k16(acc, As, Bs, wm, wn, lane);
        __syncthreads();
    }
    #pragma unroll
    for (int mt = 0; mt < 4; mt++) {
        int r0 = bm + wm + mt * 16 + (lane >> 2);
        #pragma unroll
        for (int nt = 0; nt < 4; nt++) {
            int c = bn + wn + nt * 8 + (lane & 3) * 2;
            *(float2*)&Ob[(size_t)r0 * INNER + c] =
                make_float2(acc[mt][nt][0], acc[mt][nt][1]);
            *(float2*)&Ob[(size_t)(r0 + 8) * INNER + c] =
                make_float2(acc[mt][nt][2], acc[mt][nt][3]);
        }
    }
}

// ---------------------------------------------------------------------------
// kv[h,e] = sum_c lin_k[c,h] * v[c,e]  (M=128, N=2048, K=256). grid (16, 1, NGRP)
// ---------------------------------------------------------------------------
__global__ __launch_bounds__(256, 2)
void kv_kernel(const float* __restrict__ xh,
               const float* __restrict__ glk, const float* __restrict__ blk,
               const float* __restrict__ v, float* __restrict__ kv) {
    __shared__ unsigned As[16][SMS];
    __shared__ unsigned Bs[16][SMS];
    TILE_SETUP();
    const int grp = blockIdx.z;
    const int bn = blockIdx.x * 128;
    const float* xb = xh + (size_t)grp * GROUP * HEAD;
    const float* Vb = v + (size_t)grp * GROUP * INNER;

    for (int c0 = 0; c0 < GROUP; c0 += 16) {
        // As[k=c][m=h] direct (A already k-major), with affine + tf32
        #pragma unroll
        for (int t = 0; t < 2; t++) {
            int f = tid + t * 256;
            int r = f >> 5;
            int c4 = (f & 31) * 4;
            float4 xv = *(const float4*)&xb[(size_t)(c0 + r) * HEAD + c4];
            float4 gv = *(const float4*)&glk[c4];
            float4 bv = *(const float4*)&blk[c4];
            uint4 u = make_uint4(f2tf(xv.x * gv.x + bv.x), f2tf(xv.y * gv.y + bv.y),
                                 f2tf(xv.z * gv.z + bv.z), f2tf(xv.w * gv.w + bv.w));
            *(uint4*)&As[r][c4] = u;
        }
        LOAD_B_DIRECT(*(const float4*)&Vb[(size_t)(c0 + r) * INNER + bn + c4]);
        __syncthreads();
        warp_mma_k16(acc, As, Bs, wm, wn, lane);
        __syncthreads();
    }
    float* Kb = kv + (size_t)grp * HEAD * INNER;
    #pragma unroll
    for (int mt = 0; mt < 4; mt++) {
        int h0 = wm + mt * 16 + (lane >> 2);
        #pragma unroll
        for (int nt = 0; nt < 4; nt++) {
            int e = bn + wn + nt * 8 + (lane & 3) * 2;
            *(float2*)&Kb[(size_t)h0 * INNER + e] =
                make_float2(acc[mt][nt][0], acc[mt][nt][1]);
            *(float2*)&Kb[(size_t)(h0 + 8) * INNER + e] =
                make_float2(acc[mt][nt][2], acc[mt][nt][3]);
        }
    }
}

// ---------------------------------------------------------------------------
// Exclusive cumsum of kv over the 16 chunks within each batch
// ---------------------------------------------------------------------------
__global__ void kv_cumsum_kernel(float* __restrict__ kv) {
    const int idx = blockIdx.x * blockDim.x + threadIdx.x;
    const int b = idx / (HEAD * INNER);
    const int he = idx % (HEAD * INNER);
    const int GPB = Ssz / GROUP;
    float run = 0.0f;
    for (int g = 0; g < GPB; g++) {
        size_t off = ((size_t)(b * GPB + g) * HEAD * INNER) + he;
        float t = kv[off];
        kv[off] = run;
        run += t;
    }
}

// ---------------------------------------------------------------------------
// v_lin = lin_q @ kv_excl; o = (v_quad + v_lin) * gate. grid (16, 2, NGRP)
// ---------------------------------------------------------------------------
__global__ __launch_bounds__(256, 2)
void vlin_gate_kernel(const float* __restrict__ xh,
                      const float* __restrict__ glq, const float* __restrict__ blq,
                      const float* __restrict__ kv, const float* __restrict__ gate,
                      float* __restrict__ o) {
    __shared__ unsigned As[16][SMS];
    __shared__ unsigned Bs[16][SMS];
    TILE_SETUP();
    const int grp = blockIdx.z;
    const int bm = blockIdx.y * 128, bn = blockIdx.x * 128;
    const float* xb = xh + (size_t)grp * GROUP * HEAD;
    const float* Kb = kv + (size_t)grp * HEAD * INNER;
    const float* Gb = gate + (size_t)grp * GROUP * INNER;
    float* Ob = o + (size_t)grp * GROUP * INNER;

    for (int k0 = 0; k0 < HEAD; k0 += 16) {
        #pragma unroll
        for (int t = 0; t < 2; t++) {
            int f = tid + t * 256;
            int r = f >> 2;
            int c4 = (f & 3) * 4;
            float4 xv = *(const float4*)&xb[(size_t)(bm + r) * HEAD + k0 + c4];
            float4 gv = *(const float4*)&glq[k0 + c4];
            float4 bv = *(const float4*)&blq[k0 + c4];
            As[c4 + 0][r] = f2tf(xv.x * gv.x + bv.x);
            As[c4 + 1][r] = f2tf(xv.y * gv.y + bv.y);
            As[c4 + 2][r] = f2tf(xv.z * gv.z + bv.z);
            As[c4 + 3][r] = f2tf(xv.w * gv.w + bv.w);
        }
        LOAD_B_DIRECT(*(const float4*)&Kb[(size_t)(k0 + r) * INNER + bn + c4]);
        __syncthreads();
        warp_mma_k16(acc, As, Bs, wm, wn, lane);
        __syncthreads();
    }
    #pragma unroll
    for (int mt = 0; mt < 4; mt++) {
        int r0 = bm + wm + mt * 16 + (lane >> 2);
        #pragma unroll
        for (int nt = 0; nt < 4; nt++) {
            int c = bn + wn + nt * 8 + (lane & 3) * 2;
            size_t o0 = (size_t)r0 * INNER + c;
            size_t o1 = (size_t)(r0 + 8) * INNER + c;
            float2 q0 = *(const float2*)&Ob[o0];
            float2 q1 = *(const float2*)&Ob[o1];
            float2 g0 = *(const float2*)&Gb[o0];
            float2 g1 = *(const float2*)&Gb[o1];
            *(float2*)&Ob[o0] = make_float2((q0.x + acc[mt][nt][0]) * g0.x,
                                            (q0.y + acc[mt][nt][1]) * g0.y);
            *(float2*)&Ob[o1] = make_float2((q1.x + acc[mt][nt][2]) * g1.x,
                                            (q1.y + acc[mt][nt][3]) * g1.y);
        }
    }
}

// ---------------------------------------------------------------------------
extern "C" void kernel_launch(void* const* d_in, const int* in_sizes, int n_in,
                              void* d_out, int out_size) {
    const float* x    = (const float*)d_in[0];
    const float* Wv   = (const float*)d_in[1];
    const float* bv   = (const float*)d_in[2];
    const float* Wg   = (const float*)d_in[3];
    const float* bg   = (const float*)d_in[4];
    const float* Win  = (const float*)d_in[5];
    const float* bin_ = (const float*)d_in[6];
    const float* Wout = (const float*)d_in[7];
    const float* bout = (const float*)d_in[8];
    const float* gqq  = (const float*)d_in[9];
    const float* bqq  = (const float*)d_in[10];
    const float* gqk  = (const float*)d_in[11];
    const float* bqk  = (const float*)d_in[12];
    const float* glq  = (const float*)d_in[13];
    const float* blq  = (const float*)d_in[14];
    const float* glk  = (const float*)d_in[15];
    const float* blk  = (const float*)d_in[16];
    float* out = (float*)d_out;

    float *pv, *pgate, *pxh, *po, *pattn, *pkv;
    cudaGetSymbolAddress((void**)&pv,    g_v);
    cudaGetSymbolAddress((void**)&pgate, g_gate);
    cudaGetSymbolAddress((void**)&pxh,   g_xh);
    cudaGetSymbolAddress((void**)&po,    g_o);
    cudaGetSymbolAddress((void**)&pattn, g_attn);
    cudaGetSymbolAddress((void**)&pkv,   g_kv);

    dim3 blk256(256);

    gemm_bias_act<1><<<dim3(INNER / 128, MTOT / 128), blk256>>>(x, Wv, bv, pv, MTOT, INNER, Dsz);
    gemm_bias_act<1><<<dim3(INNER / 128, MTOT / 128), blk256>>>(x, Wg, bg, pgate, MTOT, INNER, Dsz);
    gemm_bias_act<1><<<dim3(HEAD / 128, MTOT / 128), blk256>>>(x, Win, bin_, pxh, MTOT, HEAD, Dsz);

    attn_kernel<<<dim3(2, 2, NGRP), blk256>>>(pxh, gqq, bqq, gqk, bqk, pattn);
    vquad_kernel<<<dim3(INNER / 128, GROUP / 128, NGRP), blk256>>>(pattn, pv, po);
    kv_kernel<<<dim3(INNER / 128, 1, NGRP), blk256>>>(pxh, glk, blk, pv, pkv);
    kv_cumsum_kernel<<<dim3((Bsz * HEAD * INNER) / 256), blk256>>>(pkv);
    vlin_gate_kernel<<<dim3(INNER / 128, GROUP / 128, NGRP), blk256>>>(pxh, glq, blq, pkv, pgate, po);

    gemm_bias_act<0><<<dim3(Dsz / 128, MTOT / 128), blk256>>>(po, Wout, bout, out, MTOT, Dsz, INNER);
}

// round 4
// speedup vs baseline: 2.3535x; 1.1298x over previous
#include <cuda_runtime.h>
#include <cstdint>

// Problem constants
#define Bsz   4
#define Ssz   4096
#define Dsz   1024
#define GROUP 256
#define HEAD  128
#define INNER 2048
#define NGRP  (Bsz * (Ssz / GROUP))   // 64 groups
#define MTOT  (Bsz * Ssz)             // 16384 tokens

// Scratch (device globals — no allocation allowed)
__device__ float g_v   [(size_t)MTOT * INNER];
__device__ float g_gate[(size_t)MTOT * INNER];
__device__ float g_xh  [(size_t)MTOT * HEAD];
__device__ float g_o   [(size_t)MTOT * INNER];
__device__ float g_attn[(size_t)NGRP * GROUP * GROUP];
__device__ float g_kv  [(size_t)NGRP * HEAD * INNER];

__device__ __forceinline__ float silu_f(float x) { return x / (1.0f + __expf(-x)); }

__device__ __forceinline__ unsigned f2tf(float f) {
    unsigned u; asm("cvt.rna.tf32.f32 %0, %1;" : "=r"(u) : "f"(f)); return u;
}
__device__ __forceinline__ uint4 f2tf4(float4 v) {
    return make_uint4(f2tf(v.x), f2tf(v.y), f2tf(v.z), f2tf(v.w));
}
__device__ __forceinline__ uint4 f2tf4_aff(float4 v, float4 g, float4 b) {
    return make_uint4(f2tf(v.x * g.x + b.x), f2tf(v.y * g.y + b.y),
                      f2tf(v.z * g.z + b.z), f2tf(v.w * g.w + b.w));
}

__device__ __forceinline__ void mma_tf32(float c[4], const unsigned a[4], const unsigned b[2]) {
    asm("mma.sync.aligned.m16n8k8.row.col.f32.tf32.tf32.f32 "
        "{%0,%1,%2,%3}, {%4,%5,%6,%7}, {%8,%9}, {%0,%1,%2,%3};"
        : "+f"(c[0]), "+f"(c[1]), "+f"(c[2]), "+f"(c[3])
        : "r"(a[0]), "r"(a[1]), "r"(a[2]), "r"(a[3]), "r"(b[0]), "r"(b[1]));
}

// Smem tiles: [k=16][136]; stride 136 -> bank = (8k+m)%32 conflict-free
#define SMS 136

__device__ __forceinline__ void warp_mma_k16(float acc[4][4][4],
        const unsigned (*As)[SMS], const unsigned (*Bs)[SMS],
        int wm, int wn, int lane) {
    const int gm = lane >> 2;
    #pragma unroll
    for (int kk = 0; kk < 16; kk += 8) {
        const int kr = kk + (lane & 3);
        unsigned a[4][4], b[4][2];
        #pragma unroll
        for (int mt = 0; mt < 4; mt++) {
            int m = wm + mt * 16 + gm;
            a[mt][0] = As[kr][m];
            a[mt][1] = As[kr][m + 8];
            a[mt][2] = As[kr + 4][m];
            a[mt][3] = As[kr + 4][m + 8];
        }
        #pragma unroll
        for (int nt = 0; nt < 4; nt++) {
            int n = wn + nt * 8 + gm;
            b[nt][0] = Bs[kr][n];
            b[nt][1] = Bs[kr + 4][n];
        }
        #pragma unroll
        for (int mt = 0; mt < 4; mt++)
            #pragma unroll
            for (int nt = 0; nt < 4; nt++)
                mma_tf32(acc[mt][nt], a[mt], b[nt]);
    }
}

#define TILE_SETUP()                                   \
    const int tid  = threadIdx.x;                      \
    const int lane = tid & 31;                         \
    const int wid  = tid >> 5;                         \
    const int wm   = (wid >> 2) * 64;                  \
    const int wn   = (wid & 3) * 32;                   \
    float acc[4][4][4] = {};                           \
    const int ar = tid >> 2, ac = (tid & 3) * 4;       \
    const int br = tid >> 5, bc = (tid & 31) * 4;

// Store prefetched registers into stage b (A transposed layout + B direct layout)
#define STORE_AT(b)                                                           \
    As[b][ac + 0][ar] = ua0.x; As[b][ac + 1][ar] = ua0.y;                     \
    As[b][ac + 2][ar] = ua0.z; As[b][ac + 3][ar] = ua0.w;                     \
    As[b][ac + 0][ar + 64] = ua1.x; As[b][ac + 1][ar + 64] = ua1.y;           \
    As[b][ac + 2][ar + 64] = ua1.z; As[b][ac + 3][ar + 64] = ua1.w;
#define STORE_BD(b)                                                           \
    *(uint4*)&Bs[b][br][bc] = ub0; *(uint4*)&Bs[b][br + 8][bc] = ub1;

// Pipelined main loop skeleton: LOADK(k0) must fill ua0,ua1,ub0,ub1; STOREK(b) stores.
#define PIPE_LOOP(KTOT, LOADK, STOREK)                                        \
    LOADK(0); STOREK(0);                                                      \
    __syncthreads();                                                          \
    int buf = 0;                                                              \
    for (int k0 = 0; k0 < (KTOT); k0 += 16) {                                 \
        if (k0 + 16 < (KTOT)) { LOADK(k0 + 16); }                             \
        warp_mma_k16(acc, As[buf], Bs[buf], wm, wn, lane);                    \
        if (k0 + 16 < (KTOT)) {                                               \
            STOREK(buf ^ 1);                                                  \
            __syncthreads();                                                  \
            buf ^= 1;                                                         \
        }                                                                     \
    }

// ---------------------------------------------------------------------------
// Generic GEMM: C = act(A[M,K] @ W[K,N] + bias); dims % 128 == 0
// ---------------------------------------------------------------------------
template <int ACT>
__global__ __launch_bounds__(256, 2)
void gemm_bias_act(const float* __restrict__ A, const float* __restrict__ W,
                   const float* __restrict__ bias, float* __restrict__ C,
                   int M, int N, int K) {
    __shared__ unsigned As[2][16][SMS];
    __shared__ unsigned Bs[2][16][SMS];
    TILE_SETUP();
    const int bm = blockIdx.y * 128, bn = blockIdx.x * 128;
    const float* Ab = A + (size_t)bm * K;
    const float* Wb = W + bn;
    uint4 ua0, ua1, ub0, ub1;

    #define LOADK(k0)                                                         \
        ua0 = f2tf4(*(const float4*)&Ab[(size_t)ar * K + (k0) + ac]);         \
        ua1 = f2tf4(*(const float4*)&Ab[(size_t)(ar + 64) * K + (k0) + ac]);  \
        ub0 = f2tf4(*(const float4*)&Wb[(size_t)((k0) + br) * N + bc]);       \
        ub1 = f2tf4(*(const float4*)&Wb[(size_t)((k0) + br + 8) * N + bc]);
    #define STOREK(b) STORE_AT(b) STORE_BD(b)
    PIPE_LOOP(K, LOADK, STOREK)
    #undef LOADK
    #undef STOREK

    #pragma unroll
    for (int mt = 0; mt < 4; mt++) {
        int r0 = bm + wm + mt * 16 + (lane >> 2);
        #pragma unroll
        for (int nt = 0; nt < 4; nt++) {
            int c = bn + wn + nt * 8 + (lane & 3) * 2;
            float b0 = bias[c], b1 = bias[c + 1];
            float2 v0 = make_float2(acc[mt][nt][0] + b0, acc[mt][nt][1] + b1);
            float2 v1 = make_float2(acc[mt][nt][2] + b0, acc[mt][nt][3] + b1);
            if (ACT == 1) {
                v0.x = silu_f(v0.x); v0.y = silu_f(v0.y);
                v1.x = silu_f(v1.x); v1.y = silu_f(v1.y);
            }
            *(float2*)&C[(size_t)r0 * N + c] = v0;
            *(float2*)&C[(size_t)(r0 + 8) * N + c] = v1;
        }
    }
}

// ---------------------------------------------------------------------------
// attn = relu(mask(qq @ qk^T / sqrt(INNER)))^2 per group. grid (2, 2, NGRP)
// ---------------------------------------------------------------------------
__global__ __launch_bounds__(256, 2)
void attn_kernel(const float* __restrict__ xh,
                 const float* __restrict__ gqq, const float* __restrict__ bqq,
                 const float* __restrict__ gqk, const float* __restrict__ bqk,
                 float* __restrict__ attn) {
    __shared__ unsigned As[2][16][SMS];
    __shared__ unsigned Bs[2][16][SMS];
    TILE_SETUP();
    const int grp = blockIdx.z;
    const int bm = blockIdx.y * 128, bn = blockIdx.x * 128;
    const float* xb = xh + (size_t)grp * GROUP * HEAD;
    uint4 ua0, ua1, ub0, ub1;

    // Both tiles use transposed (A-style) layout; B tile fills via A-trans mapping too.
    #define LOADK(k0) {                                                       \
        float4 gq = *(const float4*)&gqq[(k0) + ac];                          \
        float4 oq = *(const float4*)&bqq[(k0) + ac];                          \
        float4 gk = *(const float4*)&gqk[(k0) + ac];                          \
        float4 ok = *(const float4*)&bqk[(k0) + ac];                          \
        ua0 = f2tf4_aff(*(const float4*)&xb[(size_t)(bm + ar) * HEAD + (k0) + ac], gq, oq);        \
        ua1 = f2tf4_aff(*(const float4*)&xb[(size_t)(bm + ar + 64) * HEAD + (k0) + ac], gq, oq);   \
        ub0 = f2tf4_aff(*(const float4*)&xb[(size_t)(bn + ar) * HEAD + (k0) + ac], gk, ok);        \
        ub1 = f2tf4_aff(*(const float4*)&xb[(size_t)(bn + ar + 64) * HEAD + (k0) + ac], gk, ok);   \
    }
    #define STOREK(b)                                                         \
        STORE_AT(b)                                                           \
        Bs[b][ac + 0][ar] = ub0.x; Bs[b][ac + 1][ar] = ub0.y;                 \
        Bs[b][ac + 2][ar] = ub0.z; Bs[b][ac + 3][ar] = ub0.w;                 \
        Bs[b][ac + 0][ar + 64] = ub1.x; Bs[b][ac + 1][ar + 64] = ub1.y;       \
        Bs[b][ac + 2][ar + 64] = ub1.z; Bs[b][ac + 3][ar + 64] = ub1.w;
    PIPE_LOOP(HEAD, LOADK, STOREK)
    #undef LOADK
    #undef STOREK

    const float inv_scale = 0.022097086912079608f;  // 1/sqrt(2048)
    float* ab = attn + (size_t)grp * GROUP * GROUP;
    #pragma unroll
    for (int mt = 0; mt < 4; mt++) {
        int r0 = bm + wm + mt * 16 + (lane >> 2);
        #pragma unroll
        for (int nt = 0; nt < 4; nt++) {
            int c = bn + wn + nt * 8 + (lane & 3) * 2;
            float s[4];
            #pragma unroll
            for (int q = 0; q < 4; q++) {
                int rr = r0 + (q >> 1) * 8;
                int cc = c + (q & 1);
                float v = acc[mt][nt][q] * inv_scale;
                s[q] = (cc <= rr && v > 0.0f) ? v * v : 0.0f;
            }
            *(float2*)&ab[(size_t)r0 * GROUP + c] = make_float2(s[0], s[1]);
            *(float2*)&ab[(size_t)(r0 + 8) * GROUP + c] = make_float2(s[2], s[3]);
        }
    }
}

// ---------------------------------------------------------------------------
// v_quad = attn @ v per group. grid (16, 2, NGRP)
// ---------------------------------------------------------------------------
__global__ __launch_bounds__(256, 2)
void vquad_kernel(const float* __restrict__ attn, const float* __restrict__ v,
                  float* __restrict__ o) {
    __shared__ unsigned As[2][16][SMS];
    __shared__ unsigned Bs[2][16][SMS];
    TILE_SETUP();
    const int grp = blockIdx.z;
    const int bm = blockIdx.y * 128, bn = blockIdx.x * 128;
    const float* Ab = attn + (size_t)grp * GROUP * GROUP + (size_t)bm * GROUP;
    const float* Vb = v + (size_t)grp * GROUP * INNER + bn;
    float* Ob = o + (size_t)grp * GROUP * INNER;
    uint4 ua0, ua1, ub0, ub1;

    #define LOADK(k0)                                                         \
        ua0 = f2tf4(*(const float4*)&Ab[(size_t)ar * GROUP + (k0) + ac]);     \
        ua1 = f2tf4(*(const float4*)&Ab[(size_t)(ar + 64) * GROUP + (k0) + ac]); \
        ub0 = f2tf4(*(const float4*)&Vb[(size_t)((k0) + br) * INNER + bc]);   \
        ub1 = f2tf4(*(const float4*)&Vb[(size_t)((k0) + br + 8) * INNER + bc]);
    #define STOREK(b) STORE_AT(b) STORE_BD(b)
    PIPE_LOOP(GROUP, LOADK, STOREK)
    #undef LOADK
    #undef STOREK

    #pragma unroll
    for (int mt = 0; mt < 4; mt++) {
        int r0 = bm + wm + mt * 16 + (lane >> 2);
        #pragma unroll
        for (int nt = 0; nt < 4; nt++) {
            int c = bn + wn + nt * 8 + (lane & 3) * 2;
            *(float2*)&Ob[(size_t)r0 * INNER + c] =
                make_float2(acc[mt][nt][0], acc[mt][nt][1]);
            *(float2*)&Ob[(size_t)(r0 + 8) * INNER + c] =
                make_float2(acc[mt][nt][2], acc[mt][nt][3]);
        }
    }
}

// ---------------------------------------------------------------------------
// kv[h,e] = sum_c lin_k[c,h] * v[c,e]  (M=128, N=2048, K=256). grid (16, 1, NGRP)
// ---------------------------------------------------------------------------
__global__ __launch_bounds__(256, 2)
void kv_kernel(const float* __restrict__ xh,
               const float* __restrict__ glk, const float* __restrict__ blk,
               const float* __restrict__ v, float* __restrict__ kv) {
    __shared__ unsigned As[2][16][SMS];
    __shared__ unsigned Bs[2][16][SMS];
    TILE_SETUP();
    const int grp = blockIdx.z;
    const int bn = blockIdx.x * 128;
    const float* xb = xh + (size_t)grp * GROUP * HEAD;
    const float* Vb = v + (size_t)grp * GROUP * INNER + bn;
    const float4 gv = *(const float4*)&glk[bc];
    const float4 bv = *(const float4*)&blk[bc];
    uint4 ua0, ua1, ub0, ub1;

    // A already k-major: As[c][h] direct via B-style mapping
    #define LOADK(k0)                                                         \
        ua0 = f2tf4_aff(*(const float4*)&xb[(size_t)((k0) + br) * HEAD + bc], gv, bv);     \
        ua1 = f2tf4_aff(*(const float4*)&xb[(size_t)((k0) + br + 8) * HEAD + bc], gv, bv); \
        ub0 = f2tf4(*(const float4*)&Vb[(size_t)((k0) + br) * INNER + bc]);   \
        ub1 = f2tf4(*(const float4*)&Vb[(size_t)((k0) + br + 8) * INNER + bc]);
    #define STOREK(b)                                                         \
        *(uint4*)&As[b][br][bc] = ua0; *(uint4*)&As[b][br + 8][bc] = ua1;     \
        STORE_BD(b)
    PIPE_LOOP(GROUP, LOADK, STOREK)
    #undef LOADK
    #undef STOREK

    float* Kb = kv + (size_t)grp * HEAD * INNER;
    #pragma unroll
    for (int mt = 0; mt < 4; mt++) {
        int h0 = wm + mt * 16 + (lane >> 2);
        #pragma unroll
        for (int nt = 0; nt < 4; nt++) {
            int e = bn + wn + nt * 8 + (lane & 3) * 2;
            *(float2*)&Kb[(size_t)h0 * INNER + e] =
                make_float2(acc[mt][nt][0], acc[mt][nt][1]);
            *(float2*)&Kb[(size_t)(h0 + 8) * INNER + e] =
                make_float2(acc[mt][nt][2], acc[mt][nt][3]);
        }
    }
}

// ---------------------------------------------------------------------------
// Exclusive cumsum of kv over the 16 chunks within each batch
// ---------------------------------------------------------------------------
__global__ void kv_cumsum_kernel(float* __restrict__ kv) {
    const int idx = blockIdx.x * blockDim.x + threadIdx.x;
    const int b = idx / (HEAD * INNER);
    const int he = idx % (HEAD * INNER);
    const int GPB = Ssz / GROUP;
    float run = 0.0f;
    for (int g = 0; g < GPB; g++) {
        size_t off = ((size_t)(b * GPB + g) * HEAD * INNER) + he;
        float t = kv[off];
        kv[off] = run;
        run += t;
    }
}

// ---------------------------------------------------------------------------
// v_lin = lin_q @ kv_excl; o = (v_quad + v_lin) * gate. grid (16, 2, NGRP)
// ---------------------------------------------------------------------------
__global__ __launch_bounds__(256, 2)
void vlin_gate_kernel(const float* __restrict__ xh,
                      const float* __restrict__ glq, const float* __restrict__ blq,
                      const float* __restrict__ kv, const float* __restrict__ gate,
                      float* __restrict__ o) {
    __shared__ unsigned As[2][16][SMS];
    __shared__ unsigned Bs[2][16][SMS];
    TILE_SETUP();
    const int grp = blockIdx.z;
    const int bm = blockIdx.y * 128, bn = blockIdx.x * 128;
    const float* xb = xh + (size_t)grp * GROUP * HEAD;
    const float* Kb = kv + (size_t)grp * HEAD * INNER + bn;
    const float* Gb = gate + (size_t)grp * GROUP * INNER;
    float* Ob = o + (size_t)grp * GROUP * INNER;
    uint4 ua0, ua1, ub0, ub1;

    #define LOADK(k0) {                                                       \
        float4 gq = *(const float4*)&glq[(k0) + ac];                          \
        float4 oq = *(const float4*)&blq[(k0) + ac];                          \
        ua0 = f2tf4_aff(*(const float4*)&xb[(size_t)(bm + ar) * HEAD + (k0) + ac], gq, oq);      \
        ua1 = f2tf4_aff(*(const float4*)&xb[(size_t)(bm + ar + 64) * HEAD + (k0) + ac], gq, oq); \
        ub0 = f2tf4(*(const float4*)&Kb[(size_t)((k0) + br) * INNER + bc]);   \
        ub1 = f2tf4(*(const float4*)&Kb[(size_t)((k0) + br + 8) * INNER + bc]); \
    }
    #define STOREK(b) STORE_AT(b) STORE_BD(b)
    PIPE_LOOP(HEAD, LOADK, STOREK)
    #undef LOADK
    #undef STOREK

    #pragma unroll
    for (int mt = 0; mt < 4; mt++) {
        int r0 = bm + wm + mt * 16 + (lane >> 2);
        #pragma unroll
        for (int nt = 0; nt < 4; nt++) {
            int c = bn + wn + nt * 8 + (lane & 3) * 2;
            size_t o0 = (size_t)r0 * INNER + c;
            size_t o1 = (size_t)(r0 + 8) * INNER + c;
            float2 q0 = *(const float2*)&Ob[o0];
            float2 q1 = *(const float2*)&Ob[o1];
            float2 g0 = *(const float2*)&Gb[o0];
            float2 g1 = *(const float2*)&Gb[o1];
            *(float2*)&Ob[o0] = make_float2((q0.x + acc[mt][nt][0]) * g0.x,
                                            (q0.y + acc[mt][nt][1]) * g0.y);
            *(float2*)&Ob[o1] = make_float2((q1.x + acc[mt][nt][2]) * g1.x,
                                            (q1.y + acc[mt][nt][3]) * g1.y);
        }
    }
}

// ---------------------------------------------------------------------------
extern "C" void kernel_launch(void* const* d_in, const int* in_sizes, int n_in,
                              void* d_out, int out_size) {
    const float* x    = (const float*)d_in[0];
    const float* Wv   = (const float*)d_in[1];
    const float* bv   = (const float*)d_in[2];
    const float* Wg   = (const float*)d_in[3];
    const float* bg   = (const float*)d_in[4];
    const float* Win  = (const float*)d_in[5];
    const float* bin_ = (const float*)d_in[6];
    const float* Wout = (const float*)d_in[7];
    const float* bout = (const float*)d_in[8];
    const float* gqq  = (const float*)d_in[9];
    const float* bqq  = (const float*)d_in[10];
    const float* gqk  = (const float*)d_in[11];
    const float* bqk  = (const float*)d_in[12];
    const float* glq  = (const float*)d_in[13];
    const float* blq  = (const float*)d_in[14];
    const float* glk  = (const float*)d_in[15];
    const float* blk  = (const float*)d_in[16];
    float* out = (float*)d_out;

    float *pv, *pgate, *pxh, *po, *pattn, *pkv;
    cudaGetSymbolAddress((void**)&pv,    g_v);
    cudaGetSymbolAddress((void**)&pgate, g_gate);
    cudaGetSymbolAddress((void**)&pxh,   g_xh);
    cudaGetSymbolAddress((void**)&po,    g_o);
    cudaGetSymbolAddress((void**)&pattn, g_attn);
    cudaGetSymbolAddress((void**)&pkv,   g_kv);

    dim3 blk256(256);

    gemm_bias_act<1><<<dim3(INNER / 128, MTOT / 128), blk256>>>(x, Wv, bv, pv, MTOT, INNER, Dsz);
    gemm_bias_act<1><<<dim3(INNER / 128, MTOT / 128), blk256>>>(x, Wg, bg, pgate, MTOT, INNER, Dsz);
    gemm_bias_act<1><<<dim3(HEAD / 128, MTOT / 128), blk256>>>(x, Win, bin_, pxh, MTOT, HEAD, Dsz);

    attn_kernel<<<dim3(2, 2, NGRP), blk256>>>(pxh, gqq, bqq, gqk, bqk, pattn);
    vquad_kernel<<<dim3(INNER / 128, GROUP / 128, NGRP), blk256>>>(pattn, pv, po);
    kv_kernel<<<dim3(INNER / 128, 1, NGRP), blk256>>>(pxh, glk, blk, pv, pkv);
    kv_cumsum_kernel<<<dim3((Bsz * HEAD * INNER) / 256), blk256>>>(pkv);
    vlin_gate_kernel<<<dim3(INNER / 128, GROUP / 128, NGRP), blk256>>>(pxh, glq, blq, pkv, pgate, po);

    gemm_bias_act<0><<<dim3(Dsz / 128, MTOT / 128), blk256>>>(po, Wout, bout, out, MTOT, Dsz, INNER);
}